// round 8
// baseline (speedup 1.0000x reference)
#include <cuda_runtime.h>
#include <math.h>

#define BTOT   65536
#define INS    360
#define L1N    180
#define NPOS   90
#define TS     32
#define KIN    33
#define HID    24
#define SAMP   8
#define THREADS 192

// ---- shared memory layout (float offsets) ----
#define OFF_W1F   0        // 30
#define OFF_B1F   30       // 6
#define OFF_W2F   36       // 216
#define OFF_B2F   252      // 12
#define OFF_RTW1  264      // 432
#define OFF_RTB1  696      // 12
#define OFF_RTW2  708      // 24
#define OFF_RTB2  732      // 4
#define OFF_FUSW  736      // 864
#define OFF_FUSB  1600     // 24
#define OFF_CW1   1624     // 288
#define OFF_CB1   1912     // 12
#define OFF_CW2   1924     // 60
#define OFF_CB2   1984     // 8
#define OFF_G     1992     // 8 * 100 (gates; also head scratch)
#define OFF_H     2792     // 8 * 28
#define OFF_SA    3016     // 8 * 12
#define OFF_SP    3112     // 8 * SSTR (conv out -> spikes; also weight staging)
#define SSTR      1156     // 32*36 + 4
#define SMEM_FLOATS (OFF_SP + SAMP * SSTR)   // 12360
#define SMEM_BYTES  (SMEM_FLOATS * 4)        // 49440

__device__ __forceinline__ float sigf(float x) {
    return __fdividef(1.0f, 1.0f + __expf(-x));
}
__device__ __forceinline__ float tanhfast(float x) {
    return fmaf(2.0f, __fdividef(1.0f, 1.0f + __expf(-2.0f * x)), -1.0f);
}

__global__ __launch_bounds__(THREADS) void fused_kernel(
    const float* __restrict__ x,
    const float* __restrict__ c1w, const float* __restrict__ c1b,
    const float* __restrict__ bn1g, const float* __restrict__ bn1b,
    const float* __restrict__ bn1m, const float* __restrict__ bn1v,
    const float* __restrict__ c2w, const float* __restrict__ c2b,
    const float* __restrict__ bn2g, const float* __restrict__ bn2b,
    const float* __restrict__ bn2m, const float* __restrict__ bn2v,
    const float* __restrict__ wih, const float* __restrict__ whh,
    const float* __restrict__ bih, const float* __restrict__ bhh,
    const float* __restrict__ rtw1, const float* __restrict__ rtb1,
    const float* __restrict__ rtw2, const float* __restrict__ rtb2,
    const float* __restrict__ fusw, const float* __restrict__ fusb,
    const float* __restrict__ cw1, const float* __restrict__ cb1,
    const float* __restrict__ cw2, const float* __restrict__ cb2,
    float* __restrict__ out)
{
    extern __shared__ float sm[];
    const int tid  = threadIdx.x;
    const int wid  = tid >> 5;
    const int lane = tid & 31;

    // ---------------- init: fold BN, load head weights, stage LSTM weights ----------------
    if (tid < 6) {
        float sc = bn1g[tid] * rsqrtf(bn1v[tid] + 1e-5f);
        #pragma unroll
        for (int r = 0; r < 5; r++) sm[OFF_W1F + tid * 5 + r] = c1w[tid * 5 + r] * sc;
        sm[OFF_B1F + tid] = (c1b[tid] - bn1m[tid]) * sc + bn1b[tid];
    } else if (tid >= 32 && tid < 44) {
        int co = tid - 32;
        float sc = bn2g[co] * rsqrtf(bn2v[co] + 1e-5f);
        #pragma unroll
        for (int i = 0; i < 18; i++) sm[OFF_W2F + co * 18 + i] = c2w[co * 18 + i] * sc;
        sm[OFF_B2F + co] = (c2b[co] - bn2m[co]) * sc + bn2b[co];
    }
    for (int i = tid; i < 432; i += THREADS) sm[OFF_RTW1 + i] = rtw1[i];
    for (int i = tid; i < 864; i += THREADS) sm[OFF_FUSW + i] = fusw[i];
    for (int i = tid; i < 288; i += THREADS) sm[OFF_CW1 + i] = cw1[i];
    if (tid < 12) sm[OFF_RTB1 + tid] = rtb1[tid];
    if (tid < 24) sm[OFF_RTW2 + tid] = rtw2[tid];
    if (tid < 2)  sm[OFF_RTB2 + tid] = rtb2[tid];
    if (tid < 24) sm[OFF_FUSB + tid] = fusb[tid];
    if (tid < 12) sm[OFF_CB1 + tid] = cb1[tid];
    if (tid < 60) sm[OFF_CW2 + tid] = cw2[tid];
    if (tid < 5)  sm[OFF_CB2 + tid] = cb2[tid];
    // stage LSTM weights into (not-yet-used) spike region
    for (int i = tid; i < 96 * KIN; i += THREADS) sm[OFF_SP + i] = wih[i];
    for (int i = tid; i < 96 * HID; i += THREADS) sm[OFF_SP + 96 * KIN + i] = whh[i];
    // zero h and sa
    if (tid < SAMP * HID + 32) { /* no-op shape helper */ }
    for (int i = tid; i < SAMP * 28; i += THREADS) sm[OFF_H + i] = 0.0f;
    for (int i = tid; i < SAMP * 12; i += THREADS) sm[OFF_SA + i] = 0.0f;
    __syncthreads();

    // ---------------- pull this thread's LSTM weight row into registers ----------------
    const int r_row = ((wid % 3) << 5) + lane;      // 0..95
    float wreg[KIN], vreg[HID];
    #pragma unroll
    for (int i = 0; i < KIN; i++) wreg[i] = sm[OFF_SP + r_row * KIN + i];
    #pragma unroll
    for (int j = 0; j < HID; j++) vreg[j] = sm[OFF_SP + 96 * KIN + r_row * HID + j];
    const float breg = bih[r_row] + bhh[r_row];
    __syncthreads();   // staging area free -> conv may overwrite

    // ---------------- conv phase: task = (sample, position) ----------------
    for (int task = tid; task < SAMP * NPOS; task += THREADS) {
        int s = task / NPOS, p = task - s * NPOS;
        const float* xr = x + (size_t)(blockIdx.x * SAMP + s) * INS;
        float c1v[3][6];
        #pragma unroll
        for (int dq = 0; dq < 3; dq++) {
            int q = 2 * p - 1 + dq;
            if (q >= 0 && q < L1N) {
                int base = 2 * q - 2;
                #pragma unroll
                for (int ci = 0; ci < 6; ci++) {
                    float acc = sm[OFF_B1F + ci];
                    #pragma unroll
                    for (int rr = 0; rr < 5; rr++) {
                        int idx = base + rr;
                        if (idx >= 0 && idx < INS)
                            acc = fmaf(sm[OFF_W1F + ci * 5 + rr], xr[idx], acc);
                    }
                    c1v[dq][ci] = fmaxf(acc, 0.0f);
                }
            } else {
                #pragma unroll
                for (int ci = 0; ci < 6; ci++) c1v[dq][ci] = 0.0f;
            }
        }
        float* conv = sm + OFF_SP + s * SSTR;
        int f0 = p * 12;
        int t  = f0 / 33;
        int k  = f0 - t * 33;
        bool store = (p < 88);
        #pragma unroll
        for (int co = 0; co < 12; co++) {
            float acc = sm[OFF_B2F + co];
            #pragma unroll
            for (int dq = 0; dq < 3; dq++)
                #pragma unroll
                for (int ci = 0; ci < 6; ci++)
                    acc = fmaf(sm[OFF_W2F + (co * 6 + ci) * 3 + dq], c1v[dq][ci], acc);
            float v = fmaxf(acc, 0.0f);
            atomicAdd(&sm[OFF_SA + s * 12 + co], v);
            if (store) conv[t * 36 + k] = v;
            if (++k == 33) { k = 0; ++t; }
        }
    }
    __syncthreads();
    if (tid < SAMP * 12) sm[OFF_SA + tid] *= (1.0f / 90.0f);

    // ---------------- LIF phase: task = (sample, k) ----------------
    for (int task = tid; task < SAMP * KIN; task += THREADS) {
        int s = task / KIN, k = task - s * KIN;
        float* base = sm + OFF_SP + s * SSTR + k;
        float m1 = 0.0f, m2 = 0.0f;
        #pragma unroll 1
        for (int t = 0; t < TS; t++) {
            float xv = base[t * 36];
            float m1n = fmaf(0.95f, m1, xv);
            bool f1 = (m1n > 0.5f);
            m1 = f1 ? 0.0f : m1n;
            float m2n = fmaf(0.9f, m2, f1 ? 1.0f : 0.0f);
            bool f2 = (m2n > 0.6f);
            m2 = f2 ? 0.0f : m2n;
            base[t * 36] = f2 ? 1.0f : 0.0f;
        }
    }
    __syncthreads();

    // ---------------- LSTM phase ----------------
    // GEMM role: warp = (rows group wid%3, sample slot q=wid/3), 4 samples each.
    // All lanes of a warp read the SAME activation addresses -> pure broadcast LDS.
    const int q4 = (wid / 3) * 4;            // first sample of this warp's slot
    // epilogue role: thread = (se, u)
    const int se = tid / 24;
    const int ue = tid - se * 24;
    float c_reg = 0.0f;

    #pragma unroll 1
    for (int t = 0; t < TS; t++) {
        #pragma unroll
        for (int ss = 0; ss < 4; ss++) {
            const int s = q4 + ss;
            const float* sp = sm + OFF_SP + s * SSTR + t * 36;
            const float* hh = sm + OFF_H + s * 28;
            const float4* s4 = (const float4*)sp;
            const float4* h4 = (const float4*)hh;
            float acc[4] = {breg, 0.0f, 0.0f, 0.0f};
            #pragma unroll
            for (int i = 0; i < 8; i++) {
                float4 f = s4[i];
                acc[i & 3] = fmaf(wreg[4 * i + 0], f.x, acc[i & 3]);
                acc[i & 3] = fmaf(wreg[4 * i + 1], f.y, acc[i & 3]);
                acc[i & 3] = fmaf(wreg[4 * i + 2], f.z, acc[i & 3]);
                acc[i & 3] = fmaf(wreg[4 * i + 3], f.w, acc[i & 3]);
            }
            acc[1] = fmaf(wreg[32], sp[32], acc[1]);
            #pragma unroll
            for (int j = 0; j < 6; j++) {
                float4 f = h4[j];
                acc[j & 3] = fmaf(vreg[4 * j + 0], f.x, acc[j & 3]);
                acc[j & 3] = fmaf(vreg[4 * j + 1], f.y, acc[j & 3]);
                acc[j & 3] = fmaf(vreg[4 * j + 2], f.z, acc[j & 3]);
                acc[j & 3] = fmaf(vreg[4 * j + 3], f.w, acc[j & 3]);
            }
            sm[OFF_G + s * 100 + r_row] = (acc[0] + acc[1]) + (acc[2] + acc[3]);
        }
        __syncthreads();
        {
            const float* g = sm + OFF_G + se * 100;
            float gi = g[ue], gf = g[24 + ue], gg = g[48 + ue], go = g[72 + ue];
            c_reg = fmaf(sigf(gf), c_reg, sigf(gi) * tanhfast(gg));
            sm[OFF_H + se * 28 + ue] = sigf(go) * tanhfast(c_reg);
        }
        __syncthreads();
    }

    // ---------------- head: warp = sample (loop) ----------------
    for (int s = wid; s < SAMP; s += 6) {
        float* g_w = sm + OFF_G + s * 100;
        const float* h_w = sm + OFF_H + s * 28;
        const float* sa_s = sm + OFF_SA + s * 12;

        if (lane < 12) {
            float acc = sm[OFF_RTB1 + lane];
            #pragma unroll
            for (int j = 0; j < 24; j++) acc = fmaf(sm[OFF_RTW1 + lane * 36 + j], h_w[j], acc);
            #pragma unroll
            for (int j = 0; j < 12; j++) acc = fmaf(sm[OFF_RTW1 + lane * 36 + 24 + j], sa_s[j], acc);
            g_w[36 + lane] = fmaxf(acc, 0.0f);
        }
        __syncwarp();
        if (lane == 0) {
            float l0 = sm[OFF_RTB2 + 0], l1 = sm[OFF_RTB2 + 1];
            #pragma unroll
            for (int j = 0; j < 12; j++) {
                float a = g_w[36 + j];
                l0 = fmaf(sm[OFF_RTW2 + j], a, l0);
                l1 = fmaf(sm[OFF_RTW2 + 12 + j], a, l1);
            }
            float mx = fmaxf(l0, l1);
            float e0 = __expf(l0 - mx), e1 = __expf(l1 - mx);
            float inv = 1.0f / (e0 + e1);
            float r0 = 0.7f * e0 * inv, r1 = 0.3f * e1 * inv;
            g_w[48] = r0 / (r0 + r1);
        }
        __syncwarp();
        float alpha = g_w[48];
        float beta  = 1.0f - alpha;
        if (lane < 24) {
            float acc = sm[OFF_FUSB + lane];
            #pragma unroll
            for (int j = 0; j < 24; j++) acc = fmaf(sm[OFF_FUSW + lane * 36 + j], h_w[j] * alpha, acc);
            #pragma unroll
            for (int j = 0; j < 12; j++) acc = fmaf(sm[OFF_FUSW + lane * 36 + 24 + j], sa_s[j] * beta, acc);
            g_w[lane] = fmaxf(acc, 0.0f);
        }
        __syncwarp();
        if (lane < 12) {
            float acc = sm[OFF_CB1 + lane];
            #pragma unroll
            for (int o = 0; o < 24; o++) acc = fmaf(sm[OFF_CW1 + lane * 24 + o], g_w[o], acc);
            g_w[64 + lane] = fmaxf(acc, 0.0f);
        }
        __syncwarp();
        if (lane < 5) {
            float acc = sm[OFF_CB2 + lane];
            #pragma unroll
            for (int i = 0; i < 12; i++) acc = fmaf(sm[OFF_CW2 + lane * 12 + i], g_w[64 + i], acc);
            out[(size_t)(blockIdx.x * SAMP + s) * 5 + lane] = acc;
        }
        __syncwarp();
    }
}

// =====================================================================
extern "C" void kernel_launch(void* const* d_in, const int* in_sizes, int n_in,
                              void* d_out, int out_size) {
    (void)in_sizes; (void)n_in; (void)out_size;
    cudaFuncSetAttribute(fused_kernel,
                         cudaFuncAttributeMaxDynamicSharedMemorySize, SMEM_BYTES);
    fused_kernel<<<BTOT / SAMP, THREADS, SMEM_BYTES>>>(
        (const float*)d_in[0],
        (const float*)d_in[1],  (const float*)d_in[2],
        (const float*)d_in[3],  (const float*)d_in[4],
        (const float*)d_in[5],  (const float*)d_in[6],
        (const float*)d_in[7],  (const float*)d_in[8],
        (const float*)d_in[9],  (const float*)d_in[10],
        (const float*)d_in[11], (const float*)d_in[12],
        (const float*)d_in[13], (const float*)d_in[14],
        (const float*)d_in[15], (const float*)d_in[16],
        (const float*)d_in[17], (const float*)d_in[18],
        (const float*)d_in[19], (const float*)d_in[20],
        (const float*)d_in[21], (const float*)d_in[22],
        (const float*)d_in[23], (const float*)d_in[24],
        (const float*)d_in[25], (const float*)d_in[26],
        (float*)d_out);
}

// round 10
// speedup vs baseline: 1.0117x; 1.0117x over previous
#include <cuda_runtime.h>
#include <math.h>

#define BTOT   65536
#define INS    360
#define L1N    180
#define NPOS   90
#define TS     32
#define KIN    33
#define HID    24
#define NSAMP  128         // samples per block
#define THREADS 128        // 4 warps; warp owns 32 samples

// ---- shared memory layout (float offsets) ----
#define OFF_W1F   0        // 30
#define OFF_B1F   30       // 6
#define OFF_W2F   36       // 216
#define OFF_B2F   252      // 12
#define OFF_WIH   264      // 96 x 36 (row padded, 16B aligned)
#define OFF_WHH   3720     // 96 x 24
#define OFF_BSUM  6024     // 96
#define OFF_RTW1  6120     // 432
#define OFF_RTB1  6552     // 12
#define OFF_RTW2  6564     // 24
#define OFF_RTB2  6588     // 4
#define OFF_FUSW  6592     // 864
#define OFF_FUSB  7456     // 24
#define OFF_CW1   7480     // 288
#define OFF_CB1   7768     // 12
#define OFF_CW2   7780     // 60
#define OFF_CB2   7840     // 8
#define OFF_SA    7848     // 12 x 128
#define OFF_MSK   9384     // uint2[32][128] = 8192 floats (8B aligned)
#define OFF_CONV  17576    // 4 rows x SSTR (one per warp)
#define SSTR      1156
#define OFF_HS    22200    // h state: 24 x 128
#define OFF_CS    25272    // c state: 24 x 128
#define SMEM_FLOATS 28344
#define SMEM_BYTES  (SMEM_FLOATS * 4)   // 113376

__device__ __forceinline__ float sigf(float x) {
    return __fdividef(1.0f, 1.0f + __expf(-x));
}
__device__ __forceinline__ float tanhfast(float x) {
    return fmaf(2.0f, __fdividef(1.0f, 1.0f + __expf(-2.0f * x)), -1.0f);
}

__global__ __launch_bounds__(THREADS) void fused_kernel(
    const float* __restrict__ x,
    const float* __restrict__ c1w, const float* __restrict__ c1b,
    const float* __restrict__ bn1g, const float* __restrict__ bn1b,
    const float* __restrict__ bn1m, const float* __restrict__ bn1v,
    const float* __restrict__ c2w, const float* __restrict__ c2b,
    const float* __restrict__ bn2g, const float* __restrict__ bn2b,
    const float* __restrict__ bn2m, const float* __restrict__ bn2v,
    const float* __restrict__ wih, const float* __restrict__ whh,
    const float* __restrict__ bih, const float* __restrict__ bhh,
    const float* __restrict__ rtw1, const float* __restrict__ rtb1,
    const float* __restrict__ rtw2, const float* __restrict__ rtb2,
    const float* __restrict__ fusw, const float* __restrict__ fusb,
    const float* __restrict__ cw1, const float* __restrict__ cb1,
    const float* __restrict__ cw2, const float* __restrict__ cb2,
    float* __restrict__ out)
{
    extern __shared__ float sm[];
    const int tid  = threadIdx.x;
    const int wid  = tid >> 5;
    const int lane = tid & 31;

    // ---------------- init: fold BN + stage weights ----------------
    if (tid < 6) {
        float sc = bn1g[tid] * rsqrtf(bn1v[tid] + 1e-5f);
        #pragma unroll
        for (int r = 0; r < 5; r++) sm[OFF_W1F + tid * 5 + r] = c1w[tid * 5 + r] * sc;
        sm[OFF_B1F + tid] = (c1b[tid] - bn1m[tid]) * sc + bn1b[tid];
    } else if (tid >= 32 && tid < 44) {
        int co = tid - 32;
        float sc = bn2g[co] * rsqrtf(bn2v[co] + 1e-5f);
        #pragma unroll
        for (int i = 0; i < 18; i++) sm[OFF_W2F + co * 18 + i] = c2w[co * 18 + i] * sc;
        sm[OFF_B2F + co] = (c2b[co] - bn2m[co]) * sc + bn2b[co];
    }
    for (int i = tid; i < 96 * KIN; i += THREADS) {
        int r = i / KIN, k = i - r * KIN;
        sm[OFF_WIH + r * 36 + k] = wih[i];
    }
    for (int i = tid; i < 96 * HID; i += THREADS) sm[OFF_WHH + i] = whh[i];
    if (tid < 96) sm[OFF_BSUM + tid] = bih[tid] + bhh[tid];
    for (int i = tid; i < 432; i += THREADS) sm[OFF_RTW1 + i] = rtw1[i];
    for (int i = tid; i < 864; i += THREADS) sm[OFF_FUSW + i] = fusw[i];
    for (int i = tid; i < 288; i += THREADS) sm[OFF_CW1 + i] = cw1[i];
    if (tid < 12) sm[OFF_RTB1 + tid] = rtb1[tid];
    if (tid < 24) sm[OFF_RTW2 + tid] = rtw2[tid];
    if (tid < 2)  sm[OFF_RTB2 + tid] = rtb2[tid];
    if (tid < 24) sm[OFF_FUSB + tid] = fusb[tid];
    if (tid < 12) sm[OFF_CB1 + tid] = cb1[tid];
    if (tid < 60) sm[OFF_CW2 + tid] = cw2[tid];
    if (tid < 5)  sm[OFF_CB2 + tid] = cb2[tid];
    for (int i = tid; i < 12 * NSAMP; i += THREADS) sm[OFF_SA + i] = 0.0f;
    // zero own h/c columns
    #pragma unroll
    for (int u = 0; u < HID; u++) {
        sm[OFF_HS + u * NSAMP + tid] = 0.0f;
        sm[OFF_CS + u * NSAMP + tid] = 0.0f;
    }
    __syncthreads();      // the ONLY block barrier

    uint2* mskp = (uint2*)(sm + OFF_MSK);

    // ---------------- conv + LIF: warp-private, 32 samples sequentially ----------------
    {
        float* scratch = sm + OFF_CONV + wid * SSTR;
        #pragma unroll 1
        for (int ss = 0; ss < 32; ss++) {
            const int s_blk = wid * 32 + ss;
            const float* xr = x + (size_t)(blockIdx.x * NSAMP + s_blk) * INS;

            float sacc[12];
            #pragma unroll
            for (int co = 0; co < 12; co++) sacc[co] = 0.0f;

            for (int p = lane; p < NPOS; p += 32) {
                float c1v[3][6];
                #pragma unroll
                for (int dq = 0; dq < 3; dq++) {
                    int q = 2 * p - 1 + dq;
                    if (q >= 0 && q < L1N) {
                        int base = 2 * q - 2;
                        #pragma unroll
                        for (int ci = 0; ci < 6; ci++) {
                            float acc = sm[OFF_B1F + ci];
                            #pragma unroll
                            for (int rr = 0; rr < 5; rr++) {
                                int idx = base + rr;
                                if (idx >= 0 && idx < INS)
                                    acc = fmaf(sm[OFF_W1F + ci * 5 + rr], xr[idx], acc);
                            }
                            c1v[dq][ci] = fmaxf(acc, 0.0f);
                        }
                    } else {
                        #pragma unroll
                        for (int ci = 0; ci < 6; ci++) c1v[dq][ci] = 0.0f;
                    }
                }
                int f0 = p * 12;
                int t  = f0 / 33;
                int k  = f0 - t * 33;
                bool store = (p < 88);
                #pragma unroll
                for (int co = 0; co < 12; co++) {
                    float acc = sm[OFF_B2F + co];
                    #pragma unroll
                    for (int dq = 0; dq < 3; dq++)
                        #pragma unroll
                        for (int ci = 0; ci < 6; ci++)
                            acc = fmaf(sm[OFF_W2F + (co * 6 + ci) * 3 + dq], c1v[dq][ci], acc);
                    float v = fmaxf(acc, 0.0f);
                    sacc[co] += v;
                    if (store) scratch[t * 36 + k] = v;
                    if (++k == 33) { k = 0; ++t; }
                }
            }
            #pragma unroll
            for (int co = 0; co < 12; co++)
                atomicAdd(&sm[OFF_SA + co * NSAMP + s_blk], sacc[co]);
            __syncwarp();

            // LIF x2, emit bit-packed spikes (lane = k; lane0 handles k=32)
            {
                float m1a = 0.0f, m2a = 0.0f, m1b = 0.0f, m2b = 0.0f;
                #pragma unroll 1
                for (int t = 0; t < TS; t++) {
                    const float* row = scratch + t * 36;
                    float xv = row[lane];
                    float m1 = fmaf(0.95f, m1a, xv);
                    bool f1 = (m1 > 0.5f);
                    m1a = f1 ? 0.0f : m1;
                    float m2 = fmaf(0.9f, m2a, f1 ? 1.0f : 0.0f);
                    bool f2 = (m2 > 0.6f);
                    m2a = f2 ? 0.0f : m2;
                    unsigned lo = __ballot_sync(0xffffffffu, f2);
                    if (lane == 0) {
                        float xb = row[32];
                        float n1 = fmaf(0.95f, m1b, xb);
                        bool g1 = (n1 > 0.5f);
                        m1b = g1 ? 0.0f : n1;
                        float n2 = fmaf(0.9f, m2b, g1 ? 1.0f : 0.0f);
                        bool g2 = (n2 > 0.6f);
                        m2b = g2 ? 0.0f : n2;
                        mskp[t * NSAMP + s_blk] = make_uint2(lo, g2 ? 1u : 0u);
                    }
                }
            }
            __syncwarp();
        }
    }
    __syncwarp();   // masks + sa written by this warp, read below by same warp

    // ---------------- LSTM: thread = sample; h/c in SMEM columns ----------------
    float* h_sm = sm + OFF_HS;
    float* c_sm = sm + OFF_CS;

    #pragma unroll 1
    for (int t = 0; t < TS; t++) {
        uint2 m = mskp[t * NSAMP + tid];
        float sp[KIN];
        #pragma unroll
        for (int k = 0; k < 32; k++) sp[k] = (m.x & (1u << k)) ? 1.0f : 0.0f;
        sp[32] = (m.y & 1u) ? 1.0f : 0.0f;

        float h[HID];
        #pragma unroll
        for (int j = 0; j < HID; j++) h[j] = h_sm[j * NSAMP + tid];

        #pragma unroll 2
        for (int u = 0; u < HID; u++) {
            const float* wi = sm + OFF_WIH + u * 36;
            const float* wf = wi + 24 * 36;
            const float* wg = wi + 48 * 36;
            const float* wo = wi + 72 * 36;
            float gi = sm[OFF_BSUM + u];
            float gf = sm[OFF_BSUM + 24 + u];
            float gg = sm[OFF_BSUM + 48 + u];
            float go = sm[OFF_BSUM + 72 + u];
            #pragma unroll
            for (int i2 = 0; i2 < 8; i2++) {
                float4 qi = ((const float4*)wi)[i2];
                float4 qf = ((const float4*)wf)[i2];
                float4 qg = ((const float4*)wg)[i2];
                float4 qo = ((const float4*)wo)[i2];
                float s0 = sp[4 * i2], s1 = sp[4 * i2 + 1];
                float s2 = sp[4 * i2 + 2], s3 = sp[4 * i2 + 3];
                gi = fmaf(qi.x, s0, gi); gi = fmaf(qi.y, s1, gi);
                gi = fmaf(qi.z, s2, gi); gi = fmaf(qi.w, s3, gi);
                gf = fmaf(qf.x, s0, gf); gf = fmaf(qf.y, s1, gf);
                gf = fmaf(qf.z, s2, gf); gf = fmaf(qf.w, s3, gf);
                gg = fmaf(qg.x, s0, gg); gg = fmaf(qg.y, s1, gg);
                gg = fmaf(qg.z, s2, gg); gg = fmaf(qg.w, s3, gg);
                go = fmaf(qo.x, s0, go); go = fmaf(qo.y, s1, go);
                go = fmaf(qo.z, s2, go); go = fmaf(qo.w, s3, go);
            }
            gi = fmaf(wi[32], sp[32], gi);
            gf = fmaf(wf[32], sp[32], gf);
            gg = fmaf(wg[32], sp[32], gg);
            go = fmaf(wo[32], sp[32], go);
            const float* vi = sm + OFF_WHH + u * 24;
            const float* vf = vi + 24 * 24;
            const float* vg = vi + 48 * 24;
            const float* vo = vi + 72 * 24;
            #pragma unroll
            for (int j2 = 0; j2 < 6; j2++) {
                float4 qi = ((const float4*)vi)[j2];
                float4 qf = ((const float4*)vf)[j2];
                float4 qg = ((const float4*)vg)[j2];
                float4 qo = ((const float4*)vo)[j2];
                float h0 = h[4 * j2], h1 = h[4 * j2 + 1];
                float h2 = h[4 * j2 + 2], h3 = h[4 * j2 + 3];
                gi = fmaf(qi.x, h0, gi); gi = fmaf(qi.y, h1, gi);
                gi = fmaf(qi.z, h2, gi); gi = fmaf(qi.w, h3, gi);
                gf = fmaf(qf.x, h0, gf); gf = fmaf(qf.y, h1, gf);
                gf = fmaf(qf.z, h2, gf); gf = fmaf(qf.w, h3, gf);
                gg = fmaf(qg.x, h0, gg); gg = fmaf(qg.y, h1, gg);
                gg = fmaf(qg.z, h2, gg); gg = fmaf(qg.w, h3, gg);
                go = fmaf(qo.x, h0, go); go = fmaf(qo.y, h1, go);
                go = fmaf(qo.z, h2, go); go = fmaf(qo.w, h3, go);
            }
            float cc = c_sm[u * NSAMP + tid];
            cc = fmaf(sigf(gf), cc, sigf(gi) * tanhfast(gg));
            c_sm[u * NSAMP + tid] = cc;
            h_sm[u * NSAMP + tid] = sigf(go) * tanhfast(cc);
        }
    }

    // ---------------- head: per-thread (thread = sample) ----------------
    float h[HID];
    #pragma unroll
    for (int j = 0; j < HID; j++) h[j] = h_sm[j * NSAMP + tid];
    float sa[12];
    #pragma unroll
    for (int ch = 0; ch < 12; ch++) sa[ch] = sm[OFF_SA + ch * NSAMP + tid] * (1.0f / 90.0f);

    float a1[12];
    #pragma unroll
    for (int i = 0; i < 12; i++) {
        float acc = sm[OFF_RTB1 + i];
        #pragma unroll
        for (int j = 0; j < 24; j++) acc = fmaf(sm[OFF_RTW1 + i * 36 + j], h[j], acc);
        #pragma unroll
        for (int j = 0; j < 12; j++) acc = fmaf(sm[OFF_RTW1 + i * 36 + 24 + j], sa[j], acc);
        a1[i] = fmaxf(acc, 0.0f);
    }
    float l0 = sm[OFF_RTB2 + 0], l1 = sm[OFF_RTB2 + 1];
    #pragma unroll
    for (int j = 0; j < 12; j++) {
        l0 = fmaf(sm[OFF_RTW2 + j], a1[j], l0);
        l1 = fmaf(sm[OFF_RTW2 + 12 + j], a1[j], l1);
    }
    float mx = fmaxf(l0, l1);
    float e0 = __expf(l0 - mx), e1 = __expf(l1 - mx);
    float inv = 1.0f / (e0 + e1);
    float r0 = 0.7f * e0 * inv, r1 = 0.3f * e1 * inv;
    float alpha = r0 / (r0 + r1);
    float beta  = 1.0f - alpha;

    float fused[24];
    #pragma unroll
    for (int o = 0; o < 24; o++) {
        float acc = sm[OFF_FUSB + o];
        #pragma unroll
        for (int j = 0; j < 24; j++) acc = fmaf(sm[OFF_FUSW + o * 36 + j], h[j] * alpha, acc);
        #pragma unroll
        for (int j = 0; j < 12; j++) acc = fmaf(sm[OFF_FUSW + o * 36 + 24 + j], sa[j] * beta, acc);
        fused[o] = fmaxf(acc, 0.0f);
    }
    float z[12];
    #pragma unroll
    for (int i = 0; i < 12; i++) {
        float acc = sm[OFF_CB1 + i];
        #pragma unroll
        for (int o = 0; o < 24; o++) acc = fmaf(sm[OFF_CW1 + i * 24 + o], fused[o], acc);
        z[i] = fmaxf(acc, 0.0f);
    }
    #pragma unroll
    for (int o = 0; o < 5; o++) {
        float acc = sm[OFF_CB2 + o];
        #pragma unroll
        for (int i = 0; i < 12; i++) acc = fmaf(sm[OFF_CW2 + o * 12 + i], z[i], acc);
        out[(size_t)(blockIdx.x * NSAMP + tid) * 5 + o] = acc;
    }
}

// =====================================================================
extern "C" void kernel_launch(void* const* d_in, const int* in_sizes, int n_in,
                              void* d_out, int out_size) {
    (void)in_sizes; (void)n_in; (void)out_size;
    cudaFuncSetAttribute(fused_kernel,
                         cudaFuncAttributeMaxDynamicSharedMemorySize, SMEM_BYTES);
    fused_kernel<<<BTOT / NSAMP, THREADS, SMEM_BYTES>>>(
        (const float*)d_in[0],
        (const float*)d_in[1],  (const float*)d_in[2],
        (const float*)d_in[3],  (const float*)d_in[4],
        (const float*)d_in[5],  (const float*)d_in[6],
        (const float*)d_in[7],  (const float*)d_in[8],
        (const float*)d_in[9],  (const float*)d_in[10],
        (const float*)d_in[11], (const float*)d_in[12],
        (const float*)d_in[13], (const float*)d_in[14],
        (const float*)d_in[15], (const float*)d_in[16],
        (const float*)d_in[17], (const float*)d_in[18],
        (const float*)d_in[19], (const float*)d_in[20],
        (const float*)d_in[21], (const float*)d_in[22],
        (const float*)d_in[23], (const float*)d_in[24],
        (const float*)d_in[25], (const float*)d_in[26],
        (float*)d_out);
}

// round 15
// speedup vs baseline: 1.7390x; 1.7188x over previous
#include <cuda_runtime.h>
#include <math.h>

#define BTOT   65536
#define INS    360
#define L1N    180
#define NPOS   90
#define TS     32
#define KIN    33
#define HID    24
#define NSAMP  128         // samples per block
#define THREADS 256        // 2 threads per sample

// ---- shared memory layout (float offsets) ----
#define OFF_W1F   0        // 30
#define OFF_B1F   30       // 6
#define OFF_W2F   36       // 216
#define OFF_B2F   252      // 12
#define OFF_WIH   264      // 96 x 36
#define OFF_WHH   3720     // 96 x 28 (stride 28: halves bank-disjoint)
#define OFF_BSUM  6408     // 96
#define OFF_RTW1  6504     // 432
#define OFF_RTB1  6936     // 12
#define OFF_RTW2  6948     // 24
#define OFF_RTB2  6972     // 4
#define OFF_FUSW  6976     // 864
#define OFF_FUSB  7840     // 24
#define OFF_CW1   7864     // 288
#define OFF_CB1   8152     // 12
#define OFF_CW2   8164     // 60
#define OFF_CB2   8224     // 8
#define OFF_SA    8232     // 12 x 128
#define OFF_MLO   9768     // uint[32][128]
#define OFF_MHI   13864    // uint[128]
#define OFF_HS    13992    // 128 x 28 (sample-major h)
#define OFF_CS    17576    // 24 x 132 (unit-major c)
#define OFF_SCR   20744    // 8 warps x 580 (16-row conv chunks)
#define SCRSTR    580
#define SMEM_FLOATS 25384
#define SMEM_BYTES  (SMEM_FLOATS * 4)   // 101536

__device__ __forceinline__ float sigf(float x) {
    return __fdividef(1.0f, 1.0f + __expf(-x));
}
__device__ __forceinline__ float tanhfast(float x) {
    return fmaf(2.0f, __fdividef(1.0f, 1.0f + __expf(-2.0f * x)), -1.0f);
}

__global__ __launch_bounds__(THREADS, 2) void fused_kernel(
    const float* __restrict__ x,
    const float* __restrict__ c1w, const float* __restrict__ c1b,
    const float* __restrict__ bn1g, const float* __restrict__ bn1b,
    const float* __restrict__ bn1m, const float* __restrict__ bn1v,
    const float* __restrict__ c2w, const float* __restrict__ c2b,
    const float* __restrict__ bn2g, const float* __restrict__ bn2b,
    const float* __restrict__ bn2m, const float* __restrict__ bn2v,
    const float* __restrict__ wih, const float* __restrict__ whh,
    const float* __restrict__ bih, const float* __restrict__ bhh,
    const float* __restrict__ rtw1, const float* __restrict__ rtb1,
    const float* __restrict__ rtw2, const float* __restrict__ rtb2,
    const float* __restrict__ fusw, const float* __restrict__ fusb,
    const float* __restrict__ cw1, const float* __restrict__ cb1,
    const float* __restrict__ cw2, const float* __restrict__ cb2,
    float* __restrict__ out)
{
    extern __shared__ float sm[];
    const int tid  = threadIdx.x;
    const int wid  = tid >> 5;
    const int lane = tid & 31;

    // ---------------- init: fold BN + stage weights ----------------
    if (tid < 6) {
        float sc = bn1g[tid] * rsqrtf(bn1v[tid] + 1e-5f);
        #pragma unroll
        for (int r = 0; r < 5; r++) sm[OFF_W1F + tid * 5 + r] = c1w[tid * 5 + r] * sc;
        sm[OFF_B1F + tid] = (c1b[tid] - bn1m[tid]) * sc + bn1b[tid];
    } else if (tid >= 32 && tid < 44) {
        int co = tid - 32;
        float sc = bn2g[co] * rsqrtf(bn2v[co] + 1e-5f);
        #pragma unroll
        for (int i = 0; i < 18; i++) sm[OFF_W2F + co * 18 + i] = c2w[co * 18 + i] * sc;
        sm[OFF_B2F + co] = (c2b[co] - bn2m[co]) * sc + bn2b[co];
    }
    for (int i = tid; i < 96 * KIN; i += THREADS) {
        int r = i / KIN, k = i - r * KIN;
        sm[OFF_WIH + r * 36 + k] = wih[i];
    }
    for (int i = tid; i < 96 * HID; i += THREADS) {
        int r = i / HID, k = i - r * HID;
        sm[OFF_WHH + r * 28 + k] = whh[i];
    }
    if (tid < 96) sm[OFF_BSUM + tid] = bih[tid] + bhh[tid];
    for (int i = tid; i < 432; i += THREADS) sm[OFF_RTW1 + i] = rtw1[i];
    for (int i = tid; i < 864; i += THREADS) sm[OFF_FUSW + i] = fusw[i];
    for (int i = tid; i < 288; i += THREADS) sm[OFF_CW1 + i] = cw1[i];
    if (tid < 12) sm[OFF_RTB1 + tid] = rtb1[tid];
    if (tid < 24) sm[OFF_RTW2 + tid] = rtw2[tid];
    if (tid < 2)  sm[OFF_RTB2 + tid] = rtb2[tid];
    if (tid < 24) sm[OFF_FUSB + tid] = fusb[tid];
    if (tid < 12) sm[OFF_CB1 + tid] = cb1[tid];
    if (tid < 60) sm[OFF_CW2 + tid] = cw2[tid];
    if (tid < 5)  sm[OFF_CB2 + tid] = cb2[tid];
    for (int i = tid; i < 12 * NSAMP; i += THREADS) sm[OFF_SA + i] = 0.0f;
    for (int i = tid; i < NSAMP * 28; i += THREADS) sm[OFF_HS + i] = 0.0f;
    for (int i = tid; i < 24 * 132; i += THREADS) sm[OFF_CS + i] = 0.0f;
    __syncthreads();

    unsigned* mlo = (unsigned*)(sm + OFF_MLO);
    unsigned* mhi = (unsigned*)(sm + OFF_MHI);

    // ---------------- conv + LIF: 8 warps, warp owns 16 samples ----------------
    {
        float* scratch = sm + OFF_SCR + wid * SCRSTR;   // 16 rows x 36
        #pragma unroll 1
        for (int ss = 0; ss < 16; ss++) {
            const int s_blk = wid * 16 + ss;
            const float* xr = x + (size_t)(blockIdx.x * NSAMP + s_blk) * INS;

            float sacc[12];
            #pragma unroll
            for (int co = 0; co < 12; co++) sacc[co] = 0.0f;
            float m1a = 0.0f, m2a = 0.0f, m1b = 0.0f, m2b = 0.0f;
            unsigned hib = 0;

            #pragma unroll 1
            for (int chunk = 0; chunk < 2; chunk++) {
                const int plim = (chunk == 0) ? 44 : 46;  // chunk1 adds p=88,89 (sa only)
                #pragma unroll 1
                for (int it = 0; it < 2; it++) {
                    int p_local = it * 32 + lane;
                    if (p_local < plim) {
                        int p = chunk * 44 + p_local;
                        float c1v[3][6];
                        #pragma unroll
                        for (int dq = 0; dq < 3; dq++) {
                            int q = 2 * p - 1 + dq;
                            if (q >= 0 && q < L1N) {
                                int base = 2 * q - 2;
                                #pragma unroll
                                for (int ci = 0; ci < 6; ci++) {
                                    float acc = sm[OFF_B1F + ci];
                                    #pragma unroll
                                    for (int rr = 0; rr < 5; rr++) {
                                        int idx = base + rr;
                                        if (idx >= 0 && idx < INS)
                                            acc = fmaf(sm[OFF_W1F + ci * 5 + rr], xr[idx], acc);
                                    }
                                    c1v[dq][ci] = fmaxf(acc, 0.0f);
                                }
                            } else {
                                #pragma unroll
                                for (int ci = 0; ci < 6; ci++) c1v[dq][ci] = 0.0f;
                            }
                        }
                        int f0 = p * 12;
                        int t  = f0 / 33;
                        int k  = f0 - t * 33;
                        bool store = (p < 88);
                        int trel = t - chunk * 16;
                        #pragma unroll
                        for (int co = 0; co < 12; co++) {
                            float acc = sm[OFF_B2F + co];
                            #pragma unroll
                            for (int dq = 0; dq < 3; dq++)
                                #pragma unroll
                                for (int ci = 0; ci < 6; ci++)
                                    acc = fmaf(sm[OFF_W2F + (co * 6 + ci) * 3 + dq], c1v[dq][ci], acc);
                            float v = fmaxf(acc, 0.0f);
                            sacc[co] += v;
                            if (store) scratch[trel * 36 + k] = v;
                            if (++k == 33) { k = 0; ++trel; }
                        }
                    }
                }
                __syncwarp();
                // LIF on this chunk's 16 rows (exact prior arithmetic)
                #pragma unroll 1
                for (int tr = 0; tr < 16; tr++) {
                    const float* row = scratch + tr * 36;
                    float xv = row[lane];
                    float m1 = fmaf(0.95f, m1a, xv);
                    bool f1 = (m1 > 0.5f);
                    m1a = f1 ? 0.0f : m1;
                    float m2 = fmaf(0.9f, m2a, f1 ? 1.0f : 0.0f);
                    bool f2 = (m2 > 0.6f);
                    m2a = f2 ? 0.0f : m2;
                    unsigned lo = __ballot_sync(0xffffffffu, f2);
                    if (lane == 0) {
                        float xb = row[32];
                        float n1 = fmaf(0.95f, m1b, xb);
                        bool g1 = (n1 > 0.5f);
                        m1b = g1 ? 0.0f : n1;
                        float n2 = fmaf(0.9f, m2b, g1 ? 1.0f : 0.0f);
                        bool g2 = (n2 > 0.6f);
                        m2b = g2 ? 0.0f : n2;
                        int tg = chunk * 16 + tr;
                        mlo[tg * NSAMP + s_blk] = lo;
                        if (g2) hib |= (1u << tg);
                    }
                }
                __syncwarp();
            }
            #pragma unroll
            for (int co = 0; co < 12; co++)
                atomicAdd(&sm[OFF_SA + co * NSAMP + s_blk], sacc[co]);
            if (lane == 0) mhi[s_blk] = hib;
        }
    }
    __syncthreads();   // masks/SA/HS/CS visible to all

    // ---------------- LSTM: 2 threads per sample, 12 units each ----------------
    const int s    = tid >> 1;
    const int half = tid & 1;
    const int u0   = half * 12;
    const unsigned hbits = mhi[s];
    float* hs = sm + OFF_HS + s * 28;
    float* cs = sm + OFF_CS;

    #pragma unroll 1
    for (int t = 0; t < TS; t++) {
        __syncwarp();   // prev-step h writes visible
        unsigned m = mlo[t * NSAMP + s];
        float sp[KIN];
        #pragma unroll
        for (int k = 0; k < 32; k++) sp[k] = (m & (1u << k)) ? 1.0f : 0.0f;
        sp[32] = ((hbits >> t) & 1u) ? 1.0f : 0.0f;

        float4 hv[6];
        #pragma unroll
        for (int j = 0; j < 6; j++) hv[j] = ((const float4*)hs)[j];
        __syncwarp();   // all reads done before anyone writes step-t h

        #pragma unroll 2
        for (int u = 0; u < 12; u++) {
            const int ua = u0 + u;
            const float* wi = sm + OFF_WIH + ua * 36;
            const float* wf = wi + 24 * 36;
            const float* wg = wi + 48 * 36;
            const float* wo = wi + 72 * 36;
            float gi = sm[OFF_BSUM + ua];
            float gf = sm[OFF_BSUM + 24 + ua];
            float gg = sm[OFF_BSUM + 48 + ua];
            float go = sm[OFF_BSUM + 72 + ua];
            #pragma unroll
            for (int i2 = 0; i2 < 8; i2++) {
                float4 qi = ((const float4*)wi)[i2];
                float4 qf = ((const float4*)wf)[i2];
                float4 qg = ((const float4*)wg)[i2];
                float4 qo = ((const float4*)wo)[i2];
                float s0 = sp[4 * i2], s1 = sp[4 * i2 + 1];
                float s2 = sp[4 * i2 + 2], s3 = sp[4 * i2 + 3];
                gi = fmaf(qi.x, s0, gi); gi = fmaf(qi.y, s1, gi);
                gi = fmaf(qi.z, s2, gi); gi = fmaf(qi.w, s3, gi);
                gf = fmaf(qf.x, s0, gf); gf = fmaf(qf.y, s1, gf);
                gf = fmaf(qf.z, s2, gf); gf = fmaf(qf.w, s3, gf);
                gg = fmaf(qg.x, s0, gg); gg = fmaf(qg.y, s1, gg);
                gg = fmaf(qg.z, s2, gg); gg = fmaf(qg.w, s3, gg);
                go = fmaf(qo.x, s0, go); go = fmaf(qo.y, s1, go);
                go = fmaf(qo.z, s2, go); go = fmaf(qo.w, s3, go);
            }
            gi = fmaf(wi[32], sp[32], gi);
            gf = fmaf(wf[32], sp[32], gf);
            gg = fmaf(wg[32], sp[32], gg);
            go = fmaf(wo[32], sp[32], go);
            const float* vi = sm + OFF_WHH + ua * 28;
            const float* vf = vi + 24 * 28;
            const float* vg = vi + 48 * 28;
            const float* vo = vi + 72 * 28;
            #pragma unroll
            for (int j2 = 0; j2 < 6; j2++) {
                float4 qi = ((const float4*)vi)[j2];
                float4 qf = ((const float4*)vf)[j2];
                float4 qg = ((const float4*)vg)[j2];
                float4 qo = ((const float4*)vo)[j2];
                float h0 = hv[j2].x, h1 = hv[j2].y, h2 = hv[j2].z, h3 = hv[j2].w;
                gi = fmaf(qi.x, h0, gi); gi = fmaf(qi.y, h1, gi);
                gi = fmaf(qi.z, h2, gi); gi = fmaf(qi.w, h3, gi);
                gf = fmaf(qf.x, h0, gf); gf = fmaf(qf.y, h1, gf);
                gf = fmaf(qf.z, h2, gf); gf = fmaf(qf.w, h3, gf);
                gg = fmaf(qg.x, h0, gg); gg = fmaf(qg.y, h1, gg);
                gg = fmaf(qg.z, h2, gg); gg = fmaf(qg.w, h3, gg);
                go = fmaf(qo.x, h0, go); go = fmaf(qo.y, h1, go);
                go = fmaf(qo.z, h2, go); go = fmaf(qo.w, h3, go);
            }
            float cc = cs[ua * 132 + s];
            cc = fmaf(sigf(gf), cc, sigf(gi) * tanhfast(gg));
            cs[ua * 132 + s] = cc;
            hs[ua] = sigf(go) * tanhfast(cc);
        }
    }
    __syncwarp();

    // ---------------- head: half==0 thread per sample ----------------
    if (half == 0) {
        float h[HID];
        #pragma unroll
        for (int j = 0; j < 6; j++) {
            float4 q = ((const float4*)hs)[j];
            h[4 * j] = q.x; h[4 * j + 1] = q.y; h[4 * j + 2] = q.z; h[4 * j + 3] = q.w;
        }
        float sa[12];
        #pragma unroll
        for (int ch = 0; ch < 12; ch++) sa[ch] = sm[OFF_SA + ch * NSAMP + s] * (1.0f / 90.0f);

        float a1[12];
        #pragma unroll
        for (int i = 0; i < 12; i++) {
            float acc = sm[OFF_RTB1 + i];
            #pragma unroll
            for (int j = 0; j < 24; j++) acc = fmaf(sm[OFF_RTW1 + i * 36 + j], h[j], acc);
            #pragma unroll
            for (int j = 0; j < 12; j++) acc = fmaf(sm[OFF_RTW1 + i * 36 + 24 + j], sa[j], acc);
            a1[i] = fmaxf(acc, 0.0f);
        }
        float l0 = sm[OFF_RTB2 + 0], l1 = sm[OFF_RTB2 + 1];
        #pragma unroll
        for (int j = 0; j < 12; j++) {
            l0 = fmaf(sm[OFF_RTW2 + j], a1[j], l0);
            l1 = fmaf(sm[OFF_RTW2 + 12 + j], a1[j], l1);
        }
        float mx = fmaxf(l0, l1);
        float e0 = __expf(l0 - mx), e1 = __expf(l1 - mx);
        float inv = 1.0f / (e0 + e1);
        float r0 = 0.7f * e0 * inv, r1 = 0.3f * e1 * inv;
        float alpha = r0 / (r0 + r1);
        float beta  = 1.0f - alpha;

        float fused[24];
        #pragma unroll
        for (int o = 0; o < 24; o++) {
            float acc = sm[OFF_FUSB + o];
            #pragma unroll
            for (int j = 0; j < 24; j++) acc = fmaf(sm[OFF_FUSW + o * 36 + j], h[j] * alpha, acc);
            #pragma unroll
            for (int j = 0; j < 12; j++) acc = fmaf(sm[OFF_FUSW + o * 36 + 24 + j], sa[j] * beta, acc);
            fused[o] = fmaxf(acc, 0.0f);
        }
        float z[12];
        #pragma unroll
        for (int i = 0; i < 12; i++) {
            float acc = sm[OFF_CB1 + i];
            #pragma unroll
            for (int o = 0; o < 24; o++) acc = fmaf(sm[OFF_CW1 + i * 24 + o], fused[o], acc);
            z[i] = fmaxf(acc, 0.0f);
        }
        #pragma unroll
        for (int o = 0; o < 5; o++) {
            float acc = sm[OFF_CB2 + o];
            #pragma unroll
            for (int i = 0; i < 12; i++) acc = fmaf(sm[OFF_CW2 + o * 12 + i], z[i], acc);
            out[(size_t)(blockIdx.x * NSAMP + s) * 5 + o] = acc;
        }
    }
}

// =====================================================================
extern "C" void kernel_launch(void* const* d_in, const int* in_sizes, int n_in,
                              void* d_out, int out_size) {
    (void)in_sizes; (void)n_in; (void)out_size;
    cudaFuncSetAttribute(fused_kernel,
                         cudaFuncAttributeMaxDynamicSharedMemorySize, SMEM_BYTES);
    fused_kernel<<<BTOT / NSAMP, THREADS, SMEM_BYTES>>>(
        (const float*)d_in[0],
        (const float*)d_in[1],  (const float*)d_in[2],
        (const float*)d_in[3],  (const float*)d_in[4],
        (const float*)d_in[5],  (const float*)d_in[6],
        (const float*)d_in[7],  (const float*)d_in[8],
        (const float*)d_in[9],  (const float*)d_in[10],
        (const float*)d_in[11], (const float*)d_in[12],
        (const float*)d_in[13], (const float*)d_in[14],
        (const float*)d_in[15], (const float*)d_in[16],
        (const float*)d_in[17], (const float*)d_in[18],
        (const float*)d_in[19], (const float*)d_in[20],
        (const float*)d_in[21], (const float*)d_in[22],
        (const float*)d_in[23], (const float*)d_in[24],
        (const float*)d_in[25], (const float*)d_in[26],
        (float*)d_out);
}